// round 2
// baseline (speedup 1.0000x reference)
#include <cuda_runtime.h>
#include <cstdint>

// out[a] += A[c] * B[d]  (elementwise over D=32), for M pairs.
// acd is int32 (JAX x64 disabled -> astype(int64) is a no-op).
// Layout: 8 threads per pair, one float4 per thread (32 floats / row).

__global__ void zero_out_kernel(float4* __restrict__ out, long long n4) {
    long long i = (long long)blockIdx.x * blockDim.x + threadIdx.x;
    long long stride = (long long)gridDim.x * blockDim.x;
    float4 z = make_float4(0.f, 0.f, 0.f, 0.f);
    for (; i < n4; i += stride) out[i] = z;
}

__global__ void __launch_bounds__(256) spspmm_kernel(
    const float4* __restrict__ A,    // [NNZ_A, 8] float4
    const float4* __restrict__ B,    // [NNZ_B, 8] float4
    const int* __restrict__ acd,     // [3, M] int32
    float* __restrict__ out,         // [tar_nnz, 32]
    long long M)
{
    long long gid = (long long)blockIdx.x * blockDim.x + threadIdx.x;
    long long pair = gid >> 3;
    int lane = (int)(gid & 7);
    if (pair >= M) return;

    long long a = (long long)__ldg(&acd[pair]);
    long long c = (long long)__ldg(&acd[M + pair]);
    long long d = (long long)__ldg(&acd[2 * M + pair]);

    float4 av = __ldg(&A[c * 8 + lane]);
    float4 bv = __ldg(&B[d * 8 + lane]);

    float4 m;
    m.x = av.x * bv.x;
    m.y = av.y * bv.y;
    m.z = av.z * bv.z;
    m.w = av.w * bv.w;

    float* dst = out + a * 32 + lane * 4;
    asm volatile(
        "red.global.add.v4.f32 [%0], {%1, %2, %3, %4};"
        :: "l"(dst), "f"(m.x), "f"(m.y), "f"(m.z), "f"(m.w)
        : "memory");
}

extern "C" void kernel_launch(void* const* d_in, const int* in_sizes, int n_in,
                              void* d_out, int out_size) {
    const float4* A = (const float4*)d_in[0];
    const float4* B = (const float4*)d_in[1];
    const int* acd = (const int*)d_in[2];
    float* out = (float*)d_out;

    long long M = (long long)in_sizes[2] / 3;

    // Zero the output (poisoned to 0xAA by the harness).
    long long n4 = (long long)out_size / 4;
    zero_out_kernel<<<1184, 256>>>((float4*)d_out, n4);

    // Main gather-multiply-scatter: 8 threads per pair.
    long long total_threads = M * 8;
    int threads = 256;
    long long blocks = (total_threads + threads - 1) / threads;
    spspmm_kernel<<<(unsigned)blocks, threads>>>(A, B, acd, out, M);
}